// round 17
// baseline (speedup 1.0000x reference)
#include <cuda_runtime.h>
#include <cuda_bf16.h>
#include <cstdint>

#define N_NODES 50000
#define N_EDGES 600000
#define NB      64
#define D       128      // F == H == U
#define NLAYERS 4

#define EPAD 132   // padded row stride for 128-wide smem tiles (global mlp)

#define LDA 136                      // bf16 row stride for W/edge-A tiles (272B)
#define WTILE_BYTES (128 * LDA * 2)  // 34816 bytes per 128x128 bf16 tile
#define ATILE_BYTES (64 * LDA * 2)   // 17408 bytes per 64x128 bf16 tile
#define NT64 (N_EDGES / 64)          // 9375 edge tiles, exact
#define NT_NODE ((N_NODES + 127) / 128)  // 391 node tiles
#define LDN_B 528                    // node A row stride bytes (264 bf16)

// ===========================================================================
// Scratch (no allocations allowed -> __device__ globals)
// ===========================================================================
__device__ float g_u[2][NB * D];
__device__ float g_agg[N_NODES * D];         // Tagg (scatter of relu'd edge hidden)
__device__ float g_cnt[N_NODES];
__device__ float g_hsum[NB * D];             // per-batch sums of node hidden h
__device__ float g_xsum[NB * D];             // xsum = hsum@W2 + bcnt*b2
__device__ float g_bcnt[NB];
__device__ float g_uprime[NB * D];
// folded fp32 weights/biases (layer 0 = originals)
__device__ float g_wc[NLAYERS][D * D];       // Wc   = n1w2_l @ W1b_l
__device__ float g_bc[NLAYERS][D];           // bc   = n1b2_l @ W1b_l
__device__ float g_ewf[NLAYERS][D * D];      // EW'_l = n2w2_{l-1} @ n1w1_l
__device__ float g_ebf[NLAYERS][D];          // eb'_l = n2b2_{l-1} @ n1w1_l + n1b1_l
__device__ float g_w1af[NLAYERS][D * D];     // W1a'_l = n2w2_{l-1} @ W1a_l
__device__ float g_b1f[NLAYERS][D];          // b1'_l  = n2b2_{l-1} @ W1a_l + n2b1_l
// h/x pre-split into bf16 hi/lo, DOUBLE BUFFERED
__device__ __align__(16) __nv_bfloat16 g_xhi[2][N_NODES * D];
__device__ __align__(16) __nv_bfloat16 g_xlo[2][N_NODES * D];
// transposed/split bf16 weight tiles [n][k]:
//  tiles 0..7  : edge EW' (layer, hi/lo)
//  tiles 8..31 : node (layer, {W1a', Wc, W2}, hi/lo)
__device__ __align__(16) unsigned char g_wt[32 * WTILE_BYTES];

__device__ __forceinline__ void red_add_v2(float* addr, float a, float b) {
    asm volatile("red.global.add.v2.f32 [%0], {%1,%2};"
                 :: "l"(addr), "f"(a), "f"(b) : "memory");
}

__device__ __forceinline__ uint32_t smem_u32(const void* p) {
    uint32_t a;
    asm("{ .reg .u64 t; cvta.to.shared.u64 t, %1; cvt.u32.u64 %0, t; }" : "=r"(a) : "l"(p));
    return a;
}

__device__ __forceinline__ void ldsm4(uint32_t addr, uint32_t r[4]) {
    asm volatile("ldmatrix.sync.aligned.m8n8.x4.shared.b16 {%0,%1,%2,%3}, [%4];"
                 : "=r"(r[0]), "=r"(r[1]), "=r"(r[2]), "=r"(r[3]) : "r"(addr));
}

__device__ __forceinline__ void mma16816(float d[4], const uint32_t a[4],
                                         uint32_t b0, uint32_t b1) {
    asm volatile(
        "mma.sync.aligned.m16n8k16.row.col.f32.bf16.bf16.f32 "
        "{%0,%1,%2,%3}, {%4,%5,%6,%7}, {%8,%9}, {%0,%1,%2,%3};"
        : "+f"(d[0]), "+f"(d[1]), "+f"(d[2]), "+f"(d[3])
        : "r"(a[0]), "r"(a[1]), "r"(a[2]), "r"(a[3]), "r"(b0), "r"(b1));
}

__device__ __forceinline__ uint32_t pack_bf16_hi(float f0, float f1) {
    return ((uint32_t)__bfloat16_as_ushort(__float2bfloat16_rn(f1)) << 16)
         |  (uint32_t)__bfloat16_as_ushort(__float2bfloat16_rn(f0));
}

#define CP_ASYNC16(dst, src) \
    asm volatile("cp.async.ca.shared.global [%0], [%1], 16;" :: "r"(dst), "l"(src) : "memory")
#define CP_ASYNC4(dst, src) \
    asm volatile("cp.async.ca.shared.global [%0], [%1], 4;"  :: "r"(dst), "l"(src) : "memory")
#define CP_COMMIT() asm volatile("cp.async.commit_group;" ::: "memory")
#define CP_WAIT0()  asm volatile("cp.async.wait_group 0;"  ::: "memory")
#define GBAR(g) asm volatile("bar.sync %0, 256;" :: "r"((g) + 1) : "memory")

// ===========================================================================
// One-time kernels
// ===========================================================================
__global__ void count_edges_kernel(const int* __restrict__ ei, float* __restrict__ cnt) {
    int e = blockIdx.x * 256 + threadIdx.x;
    if (e < N_EDGES) atomicAdd(&cnt[ei[N_EDGES + e]], 1.0f);
}
__global__ void count_batch_kernel(const int* __restrict__ batch, float* __restrict__ bcnt) {
    int n = blockIdx.x * 256 + threadIdx.x;
    if (n < N_NODES) atomicAdd(&bcnt[batch[n]], 1.0f);
}

__global__ void split_x_kernel(const float* __restrict__ x) {
    int i = blockIdx.x * 256 + threadIdx.x;
    if (i < N_NODES * (D / 2)) {
        float2 v = ((const float2*)x)[i];
        ((uint32_t*)g_xhi[0])[i] = pack_bf16_hi(v.x, v.y);
        float l0 = v.x - __bfloat162float(__float2bfloat16_rn(v.x));
        float l1 = v.y - __bfloat162float(__float2bfloat16_rn(v.y));
        ((uint32_t*)g_xlo[0])[i] = pack_bf16_hi(l0, l1);
    }
}

// Wc = n1w2 @ W1b, bc = n1b2 @ W1b (all layers)
__global__ void wc_kernel(const float* __restrict__ n1w2,
                          const float* __restrict__ n2w1,
                          const float* __restrict__ n1b2) {
    int l = blockIdx.x >> 7, k = blockIdx.x & 127, n = threadIdx.x;
    const float* w2  = n1w2 + (size_t)l * D * D;
    const float* w1b = n2w1 + (size_t)l * 384 * D + (size_t)128 * D;
    float s = 0.f;
#pragma unroll 4
    for (int j = 0; j < D; ++j)
        s = fmaf(w2[k * D + j], __ldg(&w1b[j * D + n]), s);
    g_wc[l][k * D + n] = s;
    if (k == 0) {
        float t = 0.f;
#pragma unroll 4
        for (int j = 0; j < D; ++j)
            t = fmaf(n1b2[l * D + j], __ldg(&w1b[j * D + n]), t);
        g_bc[l][n] = t;
    }
}

// Cross-layer folds: EW'_l = n2w2_{l-1}@n1w1_l, W1a'_l = n2w2_{l-1}@W1a_l (+biases).
// Layer 0 copies the originals.
__global__ void fold_kernel(const float* __restrict__ n1w1, const float* __restrict__ n1b1,
                            const float* __restrict__ n2w1, const float* __restrict__ n2b1,
                            const float* __restrict__ n2w2, const float* __restrict__ n2b2) {
    int l = blockIdx.x >> 7, j = blockIdx.x & 127, n = threadIdx.x;
    const float* ew  = n1w1 + (size_t)l * D * D;
    const float* w1a = n2w1 + (size_t)l * 384 * D;
    if (l == 0) {
        g_ewf[0][j * D + n]  = ew[j * D + n];
        g_w1af[0][j * D + n] = w1a[j * D + n];
        if (j == 0) { g_ebf[0][n] = n1b1[n]; g_b1f[0][n] = n2b1[n]; }
        return;
    }
    const float* w2 = n2w2 + (size_t)(l - 1) * D * D;
    const float* b2 = n2b2 + (size_t)(l - 1) * D;
    float s1 = 0.f, s2 = 0.f;
#pragma unroll 4
    for (int k = 0; k < D; ++k) {
        float w = w2[j * D + k];
        s1 = fmaf(w, __ldg(&ew[k * D + n]),  s1);
        s2 = fmaf(w, __ldg(&w1a[k * D + n]), s2);
    }
    g_ewf[l][j * D + n]  = s1;
    g_w1af[l][j * D + n] = s2;
    if (j == 0) {
        float t1 = 0.f, t2 = 0.f;
#pragma unroll 4
        for (int k = 0; k < D; ++k) {
            float b = b2[k];
            t1 = fmaf(b, __ldg(&ew[k * D + n]),  t1);
            t2 = fmaf(b, __ldg(&w1a[k * D + n]), t2);
        }
        g_ebf[l][n] = t1 + n1b1[l * D + n];
        g_b1f[l][n] = t2 + n2b1[l * D + n];
    }
}

// Transpose+split weights into bf16 hi/lo tiles [n][k].
// blocks 0..3 : edge EW'_l   -> tiles l*2
// blocks 4..15: node (l,j)   -> tiles 8+(l*3+j)*2 ; j: 0=W1a', 1=Wc, 2=W2
__global__ void prep_weights_kernel(const float* __restrict__ n2w2) {
    int b = blockIdx.x;
    const float* w;
    unsigned char* thi;
    if (b < 4) {
        w = g_ewf[b];
        thi = g_wt + (size_t)(b * 2) * WTILE_BYTES;
    } else {
        int bb = b - 4, l = bb / 3, j = bb % 3;
        w = (j == 0) ? g_w1af[l] : (j == 1) ? g_wc[l] : n2w2 + (size_t)l * D * D;
        thi = g_wt + (size_t)(8 + (l * 3 + j) * 2) * WTILE_BYTES;
    }
    unsigned char* tlo = thi + WTILE_BYTES;
    for (int idx = threadIdx.x; idx < 128 * 32; idx += 256) {
        int n = idx >> 5, kq = (idx & 31) << 2;
        unsigned short hh[4], ll[4];
#pragma unroll
        for (int q = 0; q < 4; ++q) {
            float f = w[(kq + q) * D + n];
            __nv_bfloat16 h = __float2bfloat16_rn(f);
            float r = f - __bfloat162float(h);
            hh[q] = __bfloat16_as_ushort(h);
            ll[q] = __bfloat16_as_ushort(__float2bfloat16_rn(r));
        }
        uint32_t o = (uint32_t)(n * LDA + kq) * 2;
        *(uint2*)(thi + o) = make_uint2(((uint32_t)hh[1] << 16) | hh[0],
                                        ((uint32_t)hh[3] << 16) | hh[2]);
        *(uint2*)(tlo + o) = make_uint2(((uint32_t)ll[1] << 16) | ll[0],
                                        ((uint32_t)ll[3] << 16) | ll[2]);
    }
}

// U' = u @ W1[256:384]
__global__ void uprime_kernel(const float* __restrict__ u, const float* __restrict__ w1u) {
    __shared__ float us[128];
    int b = blockIdx.x;
    if (threadIdx.x < 128) us[threadIdx.x] = u[b * D + threadIdx.x];
    __syncthreads();
    int n = threadIdx.x;
    float s = 0.f;
#pragma unroll 4
    for (int k = 0; k < 128; ++k)
        s = fmaf(us[k], __ldg(&w1u[k * D + n]), s);
    g_uprime[b * D + n] = s;
}

// xsum = hsum @ W2 + bcnt*b2  (64 rows)
__global__ void xsum_kernel(const float* __restrict__ hsum,
                            const float* __restrict__ bcnt,
                            const float* __restrict__ w2,
                            const float* __restrict__ b2) {
    __shared__ float hs[128];
    int b = blockIdx.x;
    if (threadIdx.x < 128) hs[threadIdx.x] = hsum[b * D + threadIdx.x];
    __syncthreads();
    int n = threadIdx.x;
    float s = 0.f;
#pragma unroll 4
    for (int k = 0; k < 128; ++k)
        s = fmaf(hs[k], __ldg(&w2[k * D + n]), s);
    g_xsum[b * D + n] = s + bcnt[b] * b2[n];
}

// ===========================================================================
// Edge kernel: T_e = relu(h[row]@EW' + eb'); Tagg[col] += T_e.
// ===========================================================================
#define SM_COLS   0                               // int[2][64]
#define SM_B1     512
#define A_OFF     2048                            // [group][hi,lo] 4 x ATILE
#define W1_HI_OFF (A_OFF + 4 * ATILE_BYTES)
#define W1_LO_OFF (W1_HI_OFF + WTILE_BYTES)
static const int EDGE_SMEM = W1_LO_OFF + WTILE_BYTES;   // 141312
#define ETHREADS 512
#define EDGE_GRID 148

__device__ __forceinline__ void gemm_split32e(uint32_t aHi, uint32_t aLo,
                                              uint32_t wHi, uint32_t wLo,
                                              int mrow, int ncol, int lane,
                                              float d[2][4][4]) {
    const int a_row  = lane & 15;
    const int a_koff = (lane >> 4) << 3;
    const int b_nrow = ((lane >> 4) << 3) + (lane & 7);
    const int b_koff = ((lane >> 3) & 1) << 3;
#pragma unroll
    for (int ks = 0; ks < 8; ++ks) {
        const int kb = ks * 16;
        uint32_t ah[2][4], al[2][4], bh[2][4], bl[2][4];
#pragma unroll
        for (int mt = 0; mt < 2; ++mt) {
            uint32_t off = (uint32_t)(((mrow + mt * 16 + a_row) * LDA + kb + a_koff) * 2);
            ldsm4(aHi + off, ah[mt]);
            ldsm4(aLo + off, al[mt]);
        }
#pragma unroll
        for (int p = 0; p < 2; ++p) {
            uint32_t off = (uint32_t)(((ncol + p * 16 + b_nrow) * LDA + kb + b_koff) * 2);
            ldsm4(wHi + off, bh[p]);
            ldsm4(wLo + off, bl[p]);
        }
#pragma unroll
        for (int p = 0; p < 2; ++p)
#pragma unroll
            for (int h = 0; h < 2; ++h)
#pragma unroll
                for (int mt = 0; mt < 2; ++mt) {
                    mma16816(d[mt][p * 2 + h], ah[mt], bh[p][2 * h], bh[p][2 * h + 1]);
                    mma16816(d[mt][p * 2 + h], ah[mt], bl[p][2 * h], bl[p][2 * h + 1]);
                    mma16816(d[mt][p * 2 + h], al[mt], bh[p][2 * h], bh[p][2 * h + 1]);
                }
    }
}

__global__ __launch_bounds__(ETHREADS, 1)
void edge_mlp_mma_kernel(const int* __restrict__ ei,
                         const __nv_bfloat16* __restrict__ xhi,
                         const __nv_bfloat16* __restrict__ xlo,
                         const unsigned char* __restrict__ w1hi, const unsigned char* __restrict__ w1lo,
                         const float* __restrict__ b1,
                         float* __restrict__ tagg)
{
    extern __shared__ char smc[];
    float* b1s = (float*)(smc + SM_B1);

    const int tid  = threadIdx.x;
    const int g    = tid >> 8;
    const int tl   = tid & 255;
    const int lw   = (tid >> 5) & 7;
    const int lane = tid & 31;

    const uint32_t sbase = smem_u32(smc);
    const uint32_t w1Hi = sbase + W1_HI_OFF, w1Lo = sbase + W1_LO_OFF;

    {
        uint4* d1h = (uint4*)(smc + W1_HI_OFF);
        uint4* d1l = (uint4*)(smc + W1_LO_OFF);
        const uint4* s1h = (const uint4*)w1hi;
        const uint4* s1l = (const uint4*)w1lo;
        for (int i = tid; i < WTILE_BYTES / 16; i += ETHREADS) {
            d1h[i] = s1h[i]; d1l[i] = s1l[i];
        }
        if (tid < 128) b1s[tid] = b1[tid];
    }
    __syncthreads();

    const uint32_t aHi = sbase + A_OFF + g * 2 * ATILE_BYTES;
    const uint32_t aLo = aHi + ATILE_BYTES;
    const int* colS = (const int*)(smc + SM_COLS + g * 256);

    const int mrow = (lw >> 2) * 32;
    const int ncol = (lw & 3) * 32;
    const int crow = lane >> 2;
    const int ccol = (lane & 3) * 2;

    const int gr = tl >> 2;
    const int gc = (tl & 3) * 64;

    for (int t = blockIdx.x * 2 + g; t < NT64; t += 2 * EDGE_GRID) {
        {
            const int e0 = t * 64;
            if (tl < 64)
                CP_ASYNC4(sbase + SM_COLS + g * 256 + tl * 4,
                          (const char*)(ei + N_EDGES + e0 + tl));
            const int src = ei[e0 + gr];
            const char* sh = (const char*)(xhi + (size_t)src * D) + gc;
            const char* sl = (const char*)(xlo + (size_t)src * D) + gc;
            const uint32_t dh = aHi + gr * (LDA * 2) + gc;
            const uint32_t dl = dh + ATILE_BYTES;
            CP_ASYNC16(dh,      sh);      CP_ASYNC16(dh + 16, sh + 16);
            CP_ASYNC16(dh + 32, sh + 32); CP_ASYNC16(dh + 48, sh + 48);
            CP_ASYNC16(dl,      sl);      CP_ASYNC16(dl + 16, sl + 16);
            CP_ASYNC16(dl + 32, sl + 32); CP_ASYNC16(dl + 48, sl + 48);
            CP_COMMIT();
            CP_WAIT0();
        }
        GBAR(g);

        float d[2][4][4];
#pragma unroll
        for (int mt = 0; mt < 2; ++mt)
#pragma unroll
            for (int nt = 0; nt < 4; ++nt)
#pragma unroll
                for (int q = 0; q < 4; ++q) d[mt][nt][q] = 0.f;

        gemm_split32e(aHi, aLo, w1Hi, w1Lo, mrow, ncol, lane, d);

#pragma unroll
        for (int mt = 0; mt < 2; ++mt) {
            const int row0 = mrow + mt * 16 + crow;
            const int c0 = colS[row0];
            const int c1 = colS[row0 + 8];
#pragma unroll
            for (int nt = 0; nt < 4; ++nt) {
                const int col = ncol + nt * 8 + ccol;
                red_add_v2(tagg + (size_t)c0 * D + col,
                           fmaxf(d[mt][nt][0] + b1s[col],     0.f),
                           fmaxf(d[mt][nt][1] + b1s[col + 1], 0.f));
                red_add_v2(tagg + (size_t)c1 * D + col,
                           fmaxf(d[mt][nt][2] + b1s[col],     0.f),
                           fmaxf(d[mt][nt][3] + b1s[col + 1], 0.f));
            }
        }
        GBAR(g);
    }
}

// ===========================================================================
// Node kernel: h = relu(hprev@W1a' + Tmean@Wc + U'[bat] + b1' + bc*(cnt>0))
// Writes split h + hsum scatter. Final layer additionally: x' = h@W2 + b2 -> out.
// ===========================================================================
#define NSM_RCP 0
#define NSM_BAT 512
#define NSM_B1  1024
#define NSM_B2  1536
#define NSM_CF  2048
#define NSM_BC  2560
#define NA_HI   3072
#define NA_LO   (NA_HI + 128 * LDN_B)
#define NW_HI   (NA_LO + 128 * LDN_B)
#define NW_LO   (NW_HI + WTILE_BYTES)
static const int NODE2_SMEM = NW_LO + WTILE_BYTES;   // 207872

__device__ __forceinline__ void gemm_split32n(uint32_t aHi, uint32_t aLo,
                                              uint32_t wHi, uint32_t wLo,
                                              int mrow, int ncol, int lane,
                                              float d[2][4][4]) {
    const int a_row  = lane & 15;
    const int a_koff = (lane >> 4) << 3;
    const int b_nrow = ((lane >> 4) << 3) + (lane & 7);
    const int b_koff = ((lane >> 3) & 1) << 3;
#pragma unroll
    for (int ks = 0; ks < 8; ++ks) {
        const int kb = ks * 16;
        uint32_t ah[2][4], al[2][4], bh[2][4], bl[2][4];
#pragma unroll
        for (int mt = 0; mt < 2; ++mt) {
            uint32_t off = (uint32_t)((mrow + mt * 16 + a_row) * LDN_B + (kb + a_koff) * 2);
            ldsm4(aHi + off, ah[mt]);
            ldsm4(aLo + off, al[mt]);
        }
#pragma unroll
        for (int p = 0; p < 2; ++p) {
            uint32_t off = (uint32_t)(((ncol + p * 16 + b_nrow) * LDA + kb + b_koff) * 2);
            ldsm4(wHi + off, bh[p]);
            ldsm4(wLo + off, bl[p]);
        }
#pragma unroll
        for (int p = 0; p < 2; ++p)
#pragma unroll
            for (int h = 0; h < 2; ++h)
#pragma unroll
                for (int mt = 0; mt < 2; ++mt) {
                    mma16816(d[mt][p * 2 + h], ah[mt], bh[p][2 * h], bh[p][2 * h + 1]);
                    mma16816(d[mt][p * 2 + h], ah[mt], bl[p][2 * h], bl[p][2 * h + 1]);
                    mma16816(d[mt][p * 2 + h], al[mt], bh[p][2 * h], bh[p][2 * h + 1]);
                }
    }
}

__global__ __launch_bounds__(512, 1)
void node_mlp_mma_kernel(const float* __restrict__ tagg,
                         const float* __restrict__ cnt,
                         const int* __restrict__ batch,
                         const __nv_bfloat16* __restrict__ xhi_r,
                         const __nv_bfloat16* __restrict__ xlo_r,
                         const unsigned char* __restrict__ wbase,  // W1a' hi/lo, Wc hi/lo, W2 hi/lo
                         const float* __restrict__ b1, const float* __restrict__ b2,
                         const float* __restrict__ bc,
                         const float* __restrict__ uprime,
                         float* __restrict__ xout,                 // non-null only on final layer
                         float* __restrict__ hsum,
                         __nv_bfloat16* __restrict__ xhi_w,
                         __nv_bfloat16* __restrict__ xlo_w)
{
    extern __shared__ char smc[];
    float* rcp = (float*)(smc + NSM_RCP);
    int*   bat = (int*)(smc + NSM_BAT);
    float* b1s = (float*)(smc + NSM_B1);
    float* b2s = (float*)(smc + NSM_B2);
    float* cfl = (float*)(smc + NSM_CF);
    float* bcs = (float*)(smc + NSM_BC);

    const uint32_t sbase = smem_u32(smc);
    const uint32_t aHi = sbase + NA_HI, aLo = sbase + NA_LO;
    const uint32_t wHi = sbase + NW_HI, wLo = sbase + NW_LO;

    const int tid = threadIdx.x, warp = tid >> 5, lane = tid & 31;
    const int n0 = blockIdx.x * 128;

    if (tid < 128) {
        int n = n0 + tid;
        if (n < N_NODES) {
            float c = cnt[n];
            rcp[tid] = 1.f / fmaxf(c, 1.f);
            cfl[tid] = (c > 0.f) ? 1.f : 0.f;
            bat[tid] = batch[n];
        } else {
            rcp[tid] = 0.f; cfl[tid] = 0.f; bat[tid] = 0;
        }
        b1s[tid] = b1[tid]; b2s[tid] = b2[tid]; bcs[tid] = bc[tid];
    }
    {
        uint4* dw = (uint4*)(smc + NW_HI);
        const uint4* sw = (const uint4*)wbase;
        for (int i = tid; i < (2 * WTILE_BYTES) / 16; i += 512) dw[i] = sw[i];
    }
    __syncthreads();

    for (int idx = tid; idx < 128 * 16; idx += 512) {
        int r = idx >> 4, q = idx & 15;
        int n = n0 + r;
        uint4 h = make_uint4(0, 0, 0, 0), l = make_uint4(0, 0, 0, 0);
        if (n < N_NODES) {
            h = *(const uint4*)(xhi_r + (size_t)n * D + q * 8);
            l = *(const uint4*)(xlo_r + (size_t)n * D + q * 8);
        }
        *(uint4*)(smc + NA_HI + r * LDN_B + q * 16) = h;
        *(uint4*)(smc + NA_LO + r * LDN_B + q * 16) = l;
    }
    for (int idx = tid; idx < 128 * 64; idx += 512) {
        int r = idx >> 6, c2 = idx & 63;
        int n = n0 + r;
        float2 v = make_float2(0.f, 0.f);
        if (n < N_NODES) v = *(const float2*)(tagg + (size_t)n * D + c2 * 2);
        float s = rcp[r];
        v.x *= s; v.y *= s;
        float l0 = v.x - __bfloat162float(__float2bfloat16_rn(v.x));
        float l1 = v.y - __bfloat162float(__float2bfloat16_rn(v.y));
        *(uint32_t*)(smc + NA_HI + r * LDN_B + 256 + c2 * 4) = pack_bf16_hi(v.x, v.y);
        *(uint32_t*)(smc + NA_LO + r * LDN_B + 256 + c2 * 4) = pack_bf16_hi(l0, l1);
    }
    __syncthreads();

    const int mrow = (warp >> 2) * 32;
    const int ncol = (warp & 3) * 32;
    const int crow = lane >> 2, ccol = (lane & 3) * 2;

    float d[2][4][4];
#pragma unroll
    for (int mt = 0; mt < 2; ++mt)
#pragma unroll
        for (int nt = 0; nt < 4; ++nt)
#pragma unroll
            for (int q = 0; q < 4; ++q) d[mt][nt][q] = 0.f;

    // GEMM1a: hprev @ W1a'
    gemm_split32n(aHi, aLo, wHi, wLo, mrow, ncol, lane, d);
    __syncthreads();
    {
        uint4* dw = (uint4*)(smc + NW_HI);
        const uint4* sw = (const uint4*)(wbase + 2 * WTILE_BYTES);
        for (int i = tid; i < (2 * WTILE_BYTES) / 16; i += 512) dw[i] = sw[i];
    }
    __syncthreads();
    // GEMM1b: Tmean @ Wc
    gemm_split32n(aHi + 256, aLo + 256, wHi, wLo, mrow, ncol, lane, d);

    // Epilogue 1: h = relu(d + b1' + U'[bat] + bc*cflag)
    //   always: split h -> global buffers, hsum scatter
    //   final:  also stash h into smem A for GEMM2
#pragma unroll
    for (int mt = 0; mt < 2; ++mt) {
        const int r0 = mrow + mt * 16 + crow, r1 = r0 + 8;
        const int nn0 = n0 + r0, nn1 = n0 + r1;
        const int bb0 = bat[r0], bb1 = bat[r1];
        const float cf0 = cfl[r0], cf1 = cfl[r1];
#pragma unroll
        for (int nt = 0; nt < 4; ++nt) {
            const int col = ncol + nt * 8 + ccol;
            float2 u0 = *(const float2*)(uprime + (size_t)bb0 * D + col);
            float2 u1 = *(const float2*)(uprime + (size_t)bb1 * D + col);
            float f0 = fmaxf(d[mt][nt][0] + b1s[col]     + u0.x + bcs[col]     * cf0, 0.f);
            float f1 = fmaxf(d[mt][nt][1] + b1s[col + 1] + u0.y + bcs[col + 1] * cf0, 0.f);
            float f2 = fmaxf(d[mt][nt][2] + b1s[col]     + u1.x + bcs[col]     * cf1, 0.f);
            float f3 = fmaxf(d[mt][nt][3] + b1s[col + 1] + u1.y + bcs[col + 1] * cf1, 0.f);
            uint32_t h01 = pack_bf16_hi(f0, f1);
            uint32_t h23 = pack_bf16_hi(f2, f3);
            float l0 = f0 - __bfloat162float(__float2bfloat16_rn(f0));
            float l1 = f1 - __bfloat162float(__float2bfloat16_rn(f1));
            float l2 = f2 - __bfloat162float(__float2bfloat16_rn(f2));
            float l3 = f3 - __bfloat162float(__float2bfloat16_rn(f3));
            uint32_t lo01 = pack_bf16_hi(l0, l1);
            uint32_t lo23 = pack_bf16_hi(l2, l3);
            if (nn0 < N_NODES) {
                *(uint32_t*)(xhi_w + (size_t)nn0 * D + col) = h01;
                *(uint32_t*)(xlo_w + (size_t)nn0 * D + col) = lo01;
                red_add_v2(hsum + (size_t)bb0 * D + col, f0, f1);
            }
            if (nn1 < N_NODES) {
                *(uint32_t*)(xhi_w + (size_t)nn1 * D + col) = h23;
                *(uint32_t*)(xlo_w + (size_t)nn1 * D + col) = lo23;
                red_add_v2(hsum + (size_t)bb1 * D + col, f2, f3);
            }
            if (xout) {
                uint32_t o0 = (uint32_t)(r0 * LDN_B + col * 2);
                uint32_t o1 = (uint32_t)(r1 * LDN_B + col * 2);
                *(uint32_t*)(smc + NA_HI + o0) = h01;
                *(uint32_t*)(smc + NA_HI + o1) = h23;
                *(uint32_t*)(smc + NA_LO + o0) = lo01;
                *(uint32_t*)(smc + NA_LO + o1) = lo23;
            }
        }
    }

    if (!xout) return;

    // ---- final layer only: x' = h @ W2 + b2 -> out ----
    __syncthreads();
    {
        uint4* dw = (uint4*)(smc + NW_HI);
        const uint4* sw = (const uint4*)(wbase + 4 * WTILE_BYTES);
        for (int i = tid; i < (2 * WTILE_BYTES) / 16; i += 512) dw[i] = sw[i];
    }
    __syncthreads();

#pragma unroll
    for (int mt = 0; mt < 2; ++mt)
#pragma unroll
        for (int nt = 0; nt < 4; ++nt)
#pragma unroll
            for (int q = 0; q < 4; ++q) d[mt][nt][q] = 0.f;

    gemm_split32n(aHi, aLo, wHi, wLo, mrow, ncol, lane, d);

#pragma unroll
    for (int mt = 0; mt < 2; ++mt) {
        const int r0 = mrow + mt * 16 + crow, r1 = r0 + 8;
        const int nn0 = n0 + r0, nn1 = n0 + r1;
#pragma unroll
        for (int nt = 0; nt < 4; ++nt) {
            const int col = ncol + nt * 8 + ccol;
            if (nn0 < N_NODES)
                *(float2*)(xout + (size_t)nn0 * D + col) =
                    make_float2(d[mt][nt][0] + b2s[col], d[mt][nt][1] + b2s[col + 1]);
            if (nn1 < N_NODES)
                *(float2*)(xout + (size_t)nn1 * D + col) =
                    make_float2(d[mt][nt][2] + b2s[col], d[mt][nt][3] + b2s[col + 1]);
        }
    }
}

// ===========================================================================
// Global MLP (unchanged)
// ===========================================================================
__global__ __launch_bounds__(256, 1)
void global_mlp_kernel(const float* __restrict__ u,
                       const float* __restrict__ xsum,
                       const float* __restrict__ bcnt,
                       const float* __restrict__ w1, const float* __restrict__ b1,
                       const float* __restrict__ w2, const float* __restrict__ b2,
                       float* __restrict__ uout)
{
    extern __shared__ float sm[];
    float* G  = sm;              // [64][256]
    float* Hh = G + 64 * 256;    // [64][EPAD]

    const int tid = threadIdx.x;
    const int tx  = tid & 15;
    const int ty  = tid >> 4;

    for (int idx = tid; idx < 64 * 128; idx += 256) {
        int b = idx >> 7, c = idx & 127;
        G[b * 256 + c]       = u[idx];
        G[b * 256 + 128 + c] = xsum[idx] / fmaxf(bcnt[b], 1.0f);
    }
    __syncthreads();

    float acc[4][8];
#pragma unroll
    for (int i = 0; i < 4; ++i)
#pragma unroll
        for (int j = 0; j < 8; ++j) acc[i][j] = 0.f;

#pragma unroll 4
    for (int k = 0; k < 256; ++k) {
        float ra[4];
#pragma unroll
        for (int i = 0; i < 4; ++i) ra[i] = G[(ty * 4 + i) * 256 + k];
        float4 rb0 = __ldg((const float4*)&w1[k * 128 + tx * 8]);
        float4 rb1 = __ldg((const float4*)&w1[k * 128 + tx * 8 + 4]);
        float rb[8] = {rb0.x, rb0.y, rb0.z, rb0.w, rb1.x, rb1.y, rb1.z, rb1.w};
#pragma unroll
        for (int i = 0; i < 4; ++i)
#pragma unroll
            for (int j = 0; j < 8; ++j) acc[i][j] = fmaf(ra[i], rb[j], acc[i][j]);
    }

    {
        float bv[8];
#pragma unroll
        for (int j = 0; j < 8; ++j) bv[j] = b1[tx * 8 + j];
#pragma unroll
        for (int i = 0; i < 4; ++i) {
#pragma unroll
            for (int j = 0; j < 8; ++j) acc[i][j] = fmaxf(acc[i][j] + bv[j], 0.f);
            *(float4*)&Hh[(ty * 4 + i) * EPAD + tx * 8]     = make_float4(acc[i][0], acc[i][1], acc[i][2], acc[i][3]);
            *(float4*)&Hh[(ty * 4 + i) * EPAD + tx * 8 + 4] = make_float4(acc[i][4], acc[i][5], acc[i][6], acc[i][7]);
        }
    }
    __syncthreads();

#pragma unroll
    for (int i = 0; i < 4; ++i)
#pragma unroll
        for (int j = 0; j < 8; ++j) acc[i][j] = 0.f;

#pragma unroll 4
    for (int k = 0; k < 128; ++k) {
        float ra[4];
#pragma unroll
        for (int i = 0; i < 4; ++i) ra[i] = Hh[(ty * 4 + i) * EPAD + k];
        float4 rb0 = __ldg((const float4*)&w2[k * 128 + tx * 8]);
        float4 rb1 = __ldg((const float4*)&w2[k * 128 + tx * 8 + 4]);
        float rb[8] = {rb0.x, rb0.y, rb0.z, rb0.w, rb1.x, rb1.y, rb1.z, rb1.w};
#pragma unroll
        for (int i = 0; i < 4; ++i)
#pragma unroll
            for (int j = 0; j < 8; ++j) acc[i][j] = fmaf(ra[i], rb[j], acc[i][j]);
    }

    {
        float bv[8];
#pragma unroll
        for (int j = 0; j < 8; ++j) bv[j] = b2[tx * 8 + j];
#pragma unroll
        for (int i = 0; i < 4; ++i) {
            int b = ty * 4 + i;
            *(float4*)&uout[b * D + tx * 8]     = make_float4(acc[i][0] + bv[0], acc[i][1] + bv[1],
                                                              acc[i][2] + bv[2], acc[i][3] + bv[3]);
            *(float4*)&uout[b * D + tx * 8 + 4] = make_float4(acc[i][4] + bv[4], acc[i][5] + bv[5],
                                                              acc[i][6] + bv[6], acc[i][7] + bv[7]);
        }
    }
}

// ===========================================================================
// Host side
// ===========================================================================
static const int GLOB_SMEM = (64 * 256 + 64 * EPAD) * 4;

extern "C" void kernel_launch(void* const* d_in, const int* in_sizes, int n_in,
                              void* d_out, int out_size) {
    const float* x0    = (const float*)d_in[0];
    const int*   ei    = (const int*)d_in[1];      // int32 (JAX x64 disabled)
    const float* u0    = (const float*)d_in[2];
    const int*   batch = (const int*)d_in[3];      // int32
    const float* n1w1 = (const float*)d_in[4];
    const float* n1b1 = (const float*)d_in[5];
    const float* n1w2 = (const float*)d_in[6];
    const float* n1b2 = (const float*)d_in[7];
    const float* n2w1 = (const float*)d_in[8];
    const float* n2b1 = (const float*)d_in[9];
    const float* n2w2 = (const float*)d_in[10];
    const float* n2b2 = (const float*)d_in[11];
    const float* gw1  = (const float*)d_in[12];
    const float* gb1  = (const float*)d_in[13];
    const float* gw2  = (const float*)d_in[14];
    const float* gb2  = (const float*)d_in[15];
    float* out = (float*)d_out;

    float *pu, *pagg, *pcnt, *phsum, *pxsum, *pbcnt, *pup, *pbc, *pebf, *pb1f;
    unsigned char* pwt;
    __nv_bfloat16 *pxhi, *pxlo;
    cudaGetSymbolAddress((void**)&pu,    g_u);
    cudaGetSymbolAddress((void**)&pagg,  g_agg);
    cudaGetSymbolAddress((void**)&pcnt,  g_cnt);
    cudaGetSymbolAddress((void**)&phsum, g_hsum);
    cudaGetSymbolAddress((void**)&pxsum, g_xsum);
    cudaGetSymbolAddress((void**)&pbcnt, g_bcnt);
    cudaGetSymbolAddress((void**)&pup,   g_uprime);
    cudaGetSymbolAddress((void**)&pbc,   g_bc);
    cudaGetSymbolAddress((void**)&pebf,  g_ebf);
    cudaGetSymbolAddress((void**)&pb1f,  g_b1f);
    cudaGetSymbolAddress((void**)&pwt,   g_wt);
    cudaGetSymbolAddress((void**)&pxhi,  g_xhi);
    cudaGetSymbolAddress((void**)&pxlo,  g_xlo);
    float* ubuf[2] = {pu, pu + (size_t)NB * D};
    __nv_bfloat16* xhib[2] = {pxhi, pxhi + (size_t)N_NODES * D};
    __nv_bfloat16* xlob[2] = {pxlo, pxlo + (size_t)N_NODES * D};

    cudaFuncSetAttribute(edge_mlp_mma_kernel, cudaFuncAttributeMaxDynamicSharedMemorySize, EDGE_SMEM);
    cudaFuncSetAttribute(node_mlp_mma_kernel, cudaFuncAttributeMaxDynamicSharedMemorySize, NODE2_SMEM);
    cudaFuncSetAttribute(global_mlp_kernel,   cudaFuncAttributeMaxDynamicSharedMemorySize, GLOB_SMEM);

    // one-time: counts, folds, weight tiles, layer-0 x split
    cudaMemsetAsync(pcnt,  0, N_NODES * sizeof(float));
    cudaMemsetAsync(pbcnt, 0, NB * sizeof(float));
    count_edges_kernel<<<(N_EDGES + 255) / 256, 256>>>(ei, pcnt);
    count_batch_kernel<<<(N_NODES + 255) / 256, 256>>>(batch, pbcnt);
    wc_kernel<<<NLAYERS * 128, 128>>>(n1w2, n2w1, n1b2);
    fold_kernel<<<NLAYERS * 128, 128>>>(n1w1, n1b1, n2w1, n2b1, n2w2, n2b2);
    prep_weights_kernel<<<16, 256>>>(n2w2);
    split_x_kernel<<<(N_NODES * (D / 2) + 255) / 256, 256>>>(x0);

    const float* uc = u0;
    for (int l = 0; l < NLAYERS; ++l) {
        const int rd = l & 1, wr = rd ^ 1;
        cudaMemsetAsync(pagg,  0, (size_t)N_NODES * D * sizeof(float));
        cudaMemsetAsync(phsum, 0, (size_t)NB * D * sizeof(float));

        const unsigned char* ewhi = pwt + (size_t)(l * 2) * WTILE_BYTES;
        const unsigned char* ewlo = ewhi + WTILE_BYTES;
        const unsigned char* nwb  = pwt + (size_t)(8 + l * 6) * WTILE_BYTES;

        edge_mlp_mma_kernel<<<EDGE_GRID, ETHREADS, EDGE_SMEM>>>(
            ei, xhib[rd], xlob[rd], ewhi, ewlo,
            pebf + (size_t)l * D, pagg);

        uprime_kernel<<<NB, 128>>>(uc, n2w1 + (size_t)l * 384 * D + 256 * D);

        float* xn = (l == NLAYERS - 1) ? out : nullptr;
        node_mlp_mma_kernel<<<NT_NODE, 512, NODE2_SMEM>>>(
            pagg, pcnt, batch, xhib[rd], xlob[rd], nwb,
            pb1f + (size_t)l * D, n2b2 + (size_t)l * D, pbc + (size_t)l * D, pup,
            xn, phsum, xhib[wr], xlob[wr]);

        xsum_kernel<<<NB, 128>>>(phsum, pbcnt,
                                 n2w2 + (size_t)l * D * D, n2b2 + (size_t)l * D);

        float* un = (l == NLAYERS - 1) ? out + (size_t)N_NODES * D : ubuf[l & 1];
        global_mlp_kernel<<<1, 256, GLOB_SMEM>>>(
            uc, pxsum, pbcnt,
            gw1 + (size_t)l * 256 * D, gb1 + (size_t)l * D,
            gw2 + (size_t)l * D * D,   gb2 + (size_t)l * D,
            un);

        uc = un;
    }
}